// round 14
// baseline (speedup 1.0000x reference)
#include <cuda_runtime.h>
#include <cuda_bf16.h>
#include <math.h>

// ---------------------------------------------------------------------------
// Problem dims
// ---------------------------------------------------------------------------
#define C2d 32
#define C1d 64
#define Td 2048
#define AVGF 32
#define SEG 64
#define Md 2048
#define TKd 3
#define HAd 16
#define DHd 128

// scratch (no allocations allowed -> __device__ globals)
__device__ float g_s[AVGF * Md];
__device__ float g_sbias[AVGF * Md];
__device__ float g_part[2100000];     // split-K partials (max 4*32*8192 = 1.05M floats)
__device__ uint4 g_afrag[65536];      // activation fragments, 2 bf16 planes, K<=8192
__device__ int   g_cnt[16];           // per-callsite grid-barrier counters

enum { EPI_LN1_SIN = 0, EPI_ATTN = 1, EPI_LN2_RES = 2, EPI_GELU = 3,
       EPI_LN1_BIAS = 4, EPI_FINAL = 5 };

// ---------------------------------------------------------------------------
// helpers: bf16 2-plane split (hi = rn(v), lo = rn(v - hi)); k-pairs packed
// into one 32-bit word (lo half = even k, hi half = odd k).
// ---------------------------------------------------------------------------
__device__ __forceinline__ void split2(float x0, float x1, unsigned& hi, unsigned& lo) {
    asm("cvt.rn.bf16x2.f32 %0, %1, %2;" : "=r"(hi) : "f"(x1), "f"(x0));
    float h0 = __uint_as_float(hi << 16);
    float h1 = __uint_as_float(hi & 0xFFFF0000u);
    float l0 = x0 - h0;
    float l1 = x1 - h1;
    asm("cvt.rn.bf16x2.f32 %0, %1, %2;" : "=r"(lo) : "f"(l1), "f"(l0));
}

__device__ __forceinline__ void mma_bf16(float c[4], unsigned a0, unsigned a1,
                                         unsigned a2, unsigned a3,
                                         unsigned b0, unsigned b1) {
    asm volatile(
        "mma.sync.aligned.m16n8k16.row.col.f32.bf16.bf16.f32 "
        "{%0,%1,%2,%3}, {%4,%5,%6,%7}, {%8,%9}, {%0,%1,%2,%3};"
        : "+f"(c[0]), "+f"(c[1]), "+f"(c[2]), "+f"(c[3])
        : "r"(a0), "r"(a1), "r"(a2), "r"(a3), "r"(b0), "r"(b1));
}

// Store one (m, even-k pair) of a [32,K] activation into the fragment layout
// read by the GEMM (inverse of the prep map; verified in earlier rounds).
__device__ __forceinline__ void st_afrag(unsigned* AF, int m, int k,
                                         unsigned hi, unsigned lo) {
    int s    = k >> 4;
    int mt   = m >> 4;
    int lane = (m & 7) * 4 + ((k & 7) >> 1);
    int j    = (((k & 15) >= 8) ? 2 : 0) + (((m & 15) >= 8) ? 1 : 0);
    unsigned* base = AF + (size_t)(s * 128 + mt * 64) * 4;
    base[lane * 4 + j]        = hi;   // plane 0
    base[(32 + lane) * 4 + j] = lo;   // plane 1
}

// ---------------------------------------------------------------------------
// block-wide sum (128 threads / 4 warps)
// ---------------------------------------------------------------------------
__device__ __forceinline__ float block_sum128(float v, float* sh) {
#pragma unroll
    for (int o = 16; o; o >>= 1) v += __shfl_xor_sync(0xFFFFFFFFu, v, o);
    int w = threadIdx.x >> 5;
    if ((threadIdx.x & 31) == 0) sh[w] = v;
    __syncthreads();
    float r = 0.f;
    if (threadIdx.x < 32) {
        r = (threadIdx.x < 4) ? sh[threadIdx.x] : 0.f;
#pragma unroll
        for (int o = 2; o; o >>= 1) r += __shfl_xor_sync(0xFFFFFFFFu, r, o);
    }
    if (threadIdx.x == 0) sh[0] = r;
    __syncthreads();
    float out = sh[0];
    __syncthreads();
    return out;
}

// ---------------------------------------------------------------------------
// Kernel 1: fused segment-average + fragment prep + sin-bias table + counter
// reset. grid (64, 16), 256 threads. Block (c1, c2h): columns k = c1*32+2*c2h
// and k+1 of altx; x rows c2*64+c1 and (c2+1)*64+c1.
// ---------------------------------------------------------------------------
__global__ void avgprep(const float* __restrict__ x, unsigned* __restrict__ AF,
                        float* __restrict__ sbias) {
    __shared__ float m0[32], m1[32];
    int tid = threadIdx.x;
    int c1 = blockIdx.x, c2 = blockIdx.y * 2;
    if (blockIdx.x == 0 && blockIdx.y == 0 && tid < 16) g_cnt[tid] = 0;

    int half = tid >> 7;           // 0 or 1
    int t = tid & 127;
    int xr = (c2 + half) * 64 + c1;
    const float* row = x + (size_t)xr * Td;
    float sum = 0.f;
#pragma unroll
    for (int j = 0; j < 16; j++) sum += row[t * 16 + j];
    // threads 4q..4q+3 (consecutive lanes) share segment q' = t>>2
    sum += __shfl_xor_sync(0xFFFFFFFFu, sum, 1);
    sum += __shfl_xor_sync(0xFFFFFFFFu, sum, 2);
    if ((t & 3) == 0) (half ? m1 : m0)[t >> 2] = sum * (1.0f / 64.0f);
    __syncthreads();

    int k = c1 * 32 + c2;   // even
    if (tid < 32) {
        unsigned hi, lo;
        split2(m0[tid], m1[tid], hi, lo);
        st_afrag(AF, tid, k, hi, lo);
    }
    if (tid < 64) {
        int i = tid >> 1;
        int c = k + (tid & 1);
        int e = c & ~1;
        float ang = (float)i * powf(10000.0f, -(float)e * (1.0f / 1024.0f));
        sbias[i * Md + c] = (c & 1) ? cosf(ang) : sinf(ang);
    }
}

// ---------------------------------------------------------------------------
// Fused split-K GEMM + grid-barrier + reduce/epilogue. No smem in mainloop.
//   partials: PART[ky, 32, N] = A[32, kslice] @ W[N, kslice]^T
// Reducers (subset of blocks, data L2-hot) then apply the stage epilogue.
// __launch_bounds__(128,4): >=4 blocks/SM -> all grids (<=512) co-resident.
// ---------------------------------------------------------------------------
template<int SPLITK, int EPI>
__global__ void __launch_bounds__(128, 4)
gemm_fused(const uint4* __restrict__ AF, const float* __restrict__ W,
           float* __restrict__ PART, int N, int K, int cntIdx,
           const float* __restrict__ bias, float* __restrict__ Sraw,
           float* __restrict__ OUT, unsigned* __restrict__ AFo,
           const float* __restrict__ lg, const float* __restrict__ lb,
           const float* __restrict__ sbias)
{
    __shared__ float sh[40];   // [0..3] warp sums / [8..39] attn rsa
    const int tid  = threadIdx.x;
    const int lane = tid & 31;
    const int warp = tid >> 5;
    const int gid  = lane >> 2;
    const int tig  = lane & 3;

    // ---------------- GEMM producer ----------------
    {
        const int n0    = blockIdx.x * 64 + warp * 16;
        const int steps = (K >> 4) / SPLITK;
        const int s0    = blockIdx.y * steps;
        const float* bp0 = W + (size_t)(n0 + gid) * K;
        const float* bp1 = W + (size_t)(n0 + 8 + gid) * K;
        const int kb = s0 * 16 + tig * 2;

        float2 b0a, b0b, b1a, b1b, x0a, x0b, x1a, x1b;
        b0a = *(const float2*)&bp0[kb];
        b0b = *(const float2*)&bp0[kb + 8];
        b1a = *(const float2*)&bp1[kb];
        b1b = *(const float2*)&bp1[kb + 8];

        float c[2][2][4] = {};
        for (int s = 0; s < steps; s++) {
            if (s + 1 < steps) {
                int kn = kb + (s + 1) * 16;
                x0a = *(const float2*)&bp0[kn];
                x0b = *(const float2*)&bp0[kn + 8];
                x1a = *(const float2*)&bp1[kn];
                x1b = *(const float2*)&bp1[kn + 8];
            }
            const uint4* af = AF + (size_t)(s0 + s) * 128;
            uint4 ah0 = af[lane];
            uint4 al0 = af[32 + lane];
            uint4 ah1 = af[64 + lane];
            uint4 al1 = af[96 + lane];

            unsigned bh00, bl00, bh01, bl01, bh10, bl10, bh11, bl11;
            split2(b0a.x, b0a.y, bh00, bl00);
            split2(b0b.x, b0b.y, bh01, bl01);
            split2(b1a.x, b1a.y, bh10, bl10);
            split2(b1b.x, b1b.y, bh11, bl11);

            mma_bf16(c[0][0], ah0.x, ah0.y, ah0.z, ah0.w, bh00, bh01);
            mma_bf16(c[0][0], ah0.x, ah0.y, ah0.z, ah0.w, bl00, bl01);
            mma_bf16(c[0][0], al0.x, al0.y, al0.z, al0.w, bh00, bh01);
            mma_bf16(c[1][0], ah1.x, ah1.y, ah1.z, ah1.w, bh00, bh01);
            mma_bf16(c[1][0], ah1.x, ah1.y, ah1.z, ah1.w, bl00, bl01);
            mma_bf16(c[1][0], al1.x, al1.y, al1.z, al1.w, bh00, bh01);
            mma_bf16(c[0][1], ah0.x, ah0.y, ah0.z, ah0.w, bh10, bh11);
            mma_bf16(c[0][1], ah0.x, ah0.y, ah0.z, ah0.w, bl10, bl11);
            mma_bf16(c[0][1], al0.x, al0.y, al0.z, al0.w, bh10, bh11);
            mma_bf16(c[1][1], ah1.x, ah1.y, ah1.z, ah1.w, bh10, bh11);
            mma_bf16(c[1][1], ah1.x, ah1.y, ah1.z, ah1.w, bl10, bl11);
            mma_bf16(c[1][1], al1.x, al1.y, al1.z, al1.w, bh10, bh11);

            b0a = x0a; b0b = x0b; b1a = x1a; b1b = x1b;
        }
        float* base = &PART[(size_t)blockIdx.y * 32 * N];
#pragma unroll
        for (int mt = 0; mt < 2; mt++)
#pragma unroll
            for (int t8 = 0; t8 < 2; t8++) {
                int col = blockIdx.x * 64 + warp * 16 + t8 * 8 + 2 * tig;
                int r0  = mt * 16 + gid;
                *(float2*)&base[r0 * N + col]       = make_float2(c[mt][t8][0], c[mt][t8][1]);
                *(float2*)&base[(r0 + 8) * N + col] = make_float2(c[mt][t8][2], c[mt][t8][3]);
            }
    }

    // ---------------- grid barrier ----------------
    const int bid   = blockIdx.y * gridDim.x + blockIdx.x;
    const int total = gridDim.x * gridDim.y;
    bool reducer;
    if (EPI == EPI_GELU)      reducer = true;
    else if (EPI == EPI_ATTN) reducer = (bid < HAd);
    else                      reducer = (bid < 32);

    __threadfence();
    __syncthreads();
    if (tid == 0) atomicAdd(&g_cnt[cntIdx], 1);
    if (!reducer) return;
    if (tid == 0) {
        while (atomicAdd(&g_cnt[cntIdx], 0) < total) __nanosleep(64);
        __threadfence();
    }
    __syncthreads();

    // ---------------- reducers ----------------
    if (EPI == EPI_ATTN) {
        // split-K reduce of qkv + scalar attention + cumsum -> afrag(imv)
        float* srsa = sh + 8;
        int h = bid;
        const float inv = 0.088388347648318447f; // 1/sqrt(128)
#pragma unroll
        for (int ii = 0; ii < 8; ii++) {
            int i = ii * 4 + warp;
            float p = 0.f;
#pragma unroll
            for (int j = 0; j < 4; j++) {
                int colq = h * DHd + lane + 32 * j;
                float qv = 0.f, kv = 0.f;
#pragma unroll
                for (int pp = 0; pp < SPLITK; pp++) {
                    const float* row = &PART[((size_t)pp * 32 + i) * (3 * Md)];
                    qv += row[colq];
                    kv += row[Md + colq];
                }
                p = fmaf(qv, kv, p);
            }
#pragma unroll
            for (int o = 16; o; o >>= 1) p += __shfl_xor_sync(0xFFFFFFFFu, p, o);
            if (lane == 0) srsa[i] = p * inv;
        }
        __syncthreads();
        if (tid < 64) {
            int colv = 2 * Md + h * DHd + tid * 2;
            float run0 = 0.f, run1 = 0.f;
#pragma unroll
            for (int i = 0; i < AVGF; i++) {
                float v0 = 0.f, v1 = 0.f;
#pragma unroll
                for (int pp = 0; pp < SPLITK; pp++) {
                    float2 vv = *(const float2*)&PART[((size_t)pp * 32 + i) * (3 * Md) + colv];
                    v0 += vv.x; v1 += vv.y;
                }
                run0 = fmaf(srsa[i], v0, run0);
                run1 = fmaf(srsa[i], v1, run1);
                unsigned hi, lo;
                split2(run0, run1, hi, lo);
                st_afrag(AFo, i, h * DHd + tid * 2, hi, lo);
            }
        }
    } else if (EPI == EPI_GELU) {
        // every block reduces its slice of [32, 8192]: bias + exact gelu -> afrag
        int idx = bid * 512 + tid * 4;
        int r = idx >> 13;
        int c = idx & 8191;
        float o[4] = {0.f, 0.f, 0.f, 0.f};
#pragma unroll
        for (int p = 0; p < SPLITK; p++) {
            float4 v = *(const float4*)&PART[((size_t)p * 32 + r) * 8192 + c];
            o[0] += v.x; o[1] += v.y; o[2] += v.z; o[3] += v.w;
        }
        float4 b = *(const float4*)&bias[c];
        o[0] += b.x; o[1] += b.y; o[2] += b.z; o[3] += b.w;
#pragma unroll
        for (int j = 0; j < 4; j++)
            o[j] = 0.5f * o[j] * (1.0f + erff(o[j] * 0.70710678118654752f));
        unsigned h0, l0, h1, l1;
        split2(o[0], o[1], h0, l0);
        split2(o[2], o[3], h1, l1);
        st_afrag(AFo, r, c, h0, l0);
        st_afrag(AFo, r, c + 2, h1, l1);
    } else {
        // N = 2048 row reduce: 32 reducer blocks, one row each, 16 cols/thread
        int r = bid;
        float o[16];
#pragma unroll
        for (int q = 0; q < 4; q++) { o[4*q] = o[4*q+1] = o[4*q+2] = o[4*q+3] = 0.f; }
#pragma unroll
        for (int p = 0; p < SPLITK; p++) {
            const float* rowp = &PART[((size_t)p * 32 + r) * Md];
#pragma unroll
            for (int q = 0; q < 4; q++) {
                float4 v = *(const float4*)&rowp[q * 512 + tid * 4];
                o[4*q] += v.x; o[4*q+1] += v.y; o[4*q+2] += v.z; o[4*q+3] += v.w;
            }
        }
        if (EPI == EPI_LN1_SIN) {
#pragma unroll
            for (int q = 0; q < 4; q++) {
                float4 v = *(const float4*)&sbias[r * Md + q * 512 + tid * 4];
                o[4*q] += v.x; o[4*q+1] += v.y; o[4*q+2] += v.z; o[4*q+3] += v.w;
            }
        }
        if (EPI == EPI_LN1_BIAS || EPI == EPI_FINAL) {
#pragma unroll
            for (int q = 0; q < 4; q++) {
                float4 v = *(const float4*)&bias[q * 512 + tid * 4];
                o[4*q] += v.x; o[4*q+1] += v.y; o[4*q+2] += v.z; o[4*q+3] += v.w;
            }
        }
        if (EPI == EPI_LN2_RES) {
#pragma unroll
            for (int q = 0; q < 4; q++) {
                float4 v = *(const float4*)&Sraw[r * Md + q * 512 + tid * 4];
                o[4*q] += v.x; o[4*q+1] += v.y; o[4*q+2] += v.z; o[4*q+3] += v.w;
            }
        }

        if (EPI == EPI_FINAL) {
#pragma unroll
            for (int q = 0; q < 4; q++)
                *(float4*)&OUT[r * Md + q * 512 + tid * 4] =
                    make_float4(o[4*q], o[4*q+1], o[4*q+2], o[4*q+3]);
            return;
        }

        float sm = 0.f;
#pragma unroll
        for (int j = 0; j < 16; j++) sm += o[j];
        float mean = block_sum128(sm, sh) * (1.0f / (float)Md);
        float sq = 0.f;
#pragma unroll
        for (int j = 0; j < 16; j++) { float d = o[j] - mean; sq += d * d; }
        float var = block_sum128(sq, sh) * (1.0f / (float)Md);
        float rstd = rsqrtf(var + 1e-5f);

        if (EPI == EPI_LN1_SIN || EPI == EPI_LN1_BIAS) {
#pragma unroll
            for (int q = 0; q < 4; q++)
                *(float4*)&Sraw[r * Md + q * 512 + tid * 4] =
                    make_float4(o[4*q], o[4*q+1], o[4*q+2], o[4*q+3]);
        }
#pragma unroll
        for (int q = 0; q < 4; q++) {
            int c = q * 512 + tid * 4;
            float yv[4];
#pragma unroll
            for (int j = 0; j < 4; j++) {
                yv[j] = (o[4*q+j] - mean) * rstd * lg[c + j] + lb[c + j];
                if (EPI == EPI_LN2_RES) yv[j] += o[4*q+j];
            }
            unsigned h0, l0, h1, l1;
            split2(yv[0], yv[1], h0, l0);
            split2(yv[2], yv[3], h1, l1);
            st_afrag(AFo, r, c, h0, l0);
            st_afrag(AFo, r, c + 2, h1, l1);
        }
    }
}

// ---------------------------------------------------------------------------
// launch
// ---------------------------------------------------------------------------
extern "C" void kernel_launch(void* const* d_in, const int* in_sizes, int n_in,
                              void* d_out, int out_size) {
    const float* x      = (const float*)d_in[0];
    const float* weight = (const float*)d_in[1];
    const float* Wqkv   = (const float*)d_in[2];
    const float* Wo     = (const float*)d_in[3];
    const float* ln1_g  = (const float*)d_in[4];
    const float* ln1_b  = (const float*)d_in[5];
    const float* ln2_g  = (const float*)d_in[6];
    const float* ln2_b  = (const float*)d_in[7];
    const float* fc1_w  = (const float*)d_in[8];
    const float* fc1_b  = (const float*)d_in[9];
    const float* fc2_w  = (const float*)d_in[10];
    const float* fc2_b  = (const float*)d_in[11];
    float* out = (float*)d_out;

    float *s, *part, *sbias;
    uint4* afrag;
    cudaGetSymbolAddress((void**)&s,     g_s);
    cudaGetSymbolAddress((void**)&part,  g_part);
    cudaGetSymbolAddress((void**)&sbias, g_sbias);
    cudaGetSymbolAddress((void**)&afrag, g_afrag);
    unsigned* afw = (unsigned*)afrag;

    // 1) fused segment-average + A-frag prep + sin-bias table + counter reset
    avgprep<<<dim3(C1d, 16), 256>>>(x, afw, sbias);

    // 2) s = altx @ weight^T + sin; afrag <- LN1(s)
    gemm_fused<8, EPI_LN1_SIN><<<dim3(Md / 64, 8), 128>>>(
        afrag, weight, part, Md, Md, 0,
        nullptr, s, nullptr, afw, ln1_g, ln1_b, sbias);

    for (int a = 0; a < TKd; a++) {
        int ci = 1 + 4 * a;
        // qkv partials + attention + cumsum -> afrag(imv)
        gemm_fused<4, EPI_ATTN><<<dim3((3 * Md) / 64, 4), 128>>>(
            afrag, Wqkv + (size_t)a * 3 * Md * Md, part, 3 * Md, Md, ci,
            nullptr, nullptr, nullptr, afw, nullptr, nullptr, nullptr);

        // s' = imv @ Wo^T + s;  afrag <- LN2(s') + s'
        gemm_fused<8, EPI_LN2_RES><<<dim3(Md / 64, 8), 128>>>(
            afrag, Wo + (size_t)a * Md * Md, part, Md, Md, ci + 1,
            nullptr, s, nullptr, afw, ln2_g, ln2_b, nullptr);

        // h = gelu(s'' @ fc1^T + b) -> afrag
        gemm_fused<4, EPI_GELU><<<dim3((4 * Md) / 64, 4), 128>>>(
            afrag, fc1_w, part, 4 * Md, Md, ci + 2,
            fc1_b, nullptr, nullptr, afw, nullptr, nullptr, nullptr);

        // s = h @ fc2^T + b  (+ next LN1, or final store)
        if (a < TKd - 1) {
            gemm_fused<8, EPI_LN1_BIAS><<<dim3(Md / 64, 8), 128>>>(
                afrag, fc2_w, part, Md, 4 * Md, ci + 3,
                fc2_b, s, nullptr, afw, ln1_g, ln1_b, nullptr);
        } else {
            gemm_fused<8, EPI_FINAL><<<dim3(Md / 64, 8), 128>>>(
                afrag, fc2_w, part, Md, 4 * Md, ci + 3,
                fc2_b, nullptr, out, nullptr, nullptr, nullptr, nullptr);
        }
    }
}

// round 15
// speedup vs baseline: 1.0933x; 1.0933x over previous
#include <cuda_runtime.h>
#include <cuda_bf16.h>
#include <math.h>

// ---------------------------------------------------------------------------
// Problem dims
// ---------------------------------------------------------------------------
#define C2d 32
#define C1d 64
#define Td 2048
#define AVGF 32
#define SEG 64
#define Md 2048
#define TKd 3
#define HAd 16
#define DHd 128

// scratch (no allocations allowed -> __device__ globals)
__device__ float g_altx[AVGF * Md];
__device__ float g_s[AVGF * Md];
__device__ float g_part[2100000];     // split-K partials
__device__ uint4 g_afrag[65536];      // activation fragments, 2 bf16 planes

#define F_BIAS 1
#define F_RES  2
#define F_GELU 4
#define F_SIN  8

// ---------------------------------------------------------------------------
// helpers: bf16 2-plane split (hi = rn(v), lo = rn(v - hi)); k-pairs packed
// into one 32-bit word (lo half = even k, hi half = odd k).
// ---------------------------------------------------------------------------
__device__ __forceinline__ void split2(float x0, float x1, unsigned& hi, unsigned& lo) {
    asm("cvt.rn.bf16x2.f32 %0, %1, %2;" : "=r"(hi) : "f"(x1), "f"(x0));
    float h0 = __uint_as_float(hi << 16);
    float h1 = __uint_as_float(hi & 0xFFFF0000u);
    float l0 = x0 - h0;
    float l1 = x1 - h1;
    asm("cvt.rn.bf16x2.f32 %0, %1, %2;" : "=r"(lo) : "f"(l1), "f"(l0));
}

__device__ __forceinline__ void mma_bf16(float c[4], unsigned a0, unsigned a1,
                                         unsigned a2, unsigned a3,
                                         unsigned b0, unsigned b1) {
    asm volatile(
        "mma.sync.aligned.m16n8k16.row.col.f32.bf16.bf16.f32 "
        "{%0,%1,%2,%3}, {%4,%5,%6,%7}, {%8,%9}, {%0,%1,%2,%3};"
        : "+f"(c[0]), "+f"(c[1]), "+f"(c[2]), "+f"(c[3])
        : "r"(a0), "r"(a1), "r"(a2), "r"(a3), "r"(b0), "r"(b1));
}

// Store one (m, even-k pair) of a [32,K] activation into the fragment layout
// read by gemm_v2 (inverse of prep_afrag's map; verified in earlier rounds).
__device__ __forceinline__ void st_afrag(unsigned* AF, int m, int k,
                                         unsigned hi, unsigned lo) {
    int s    = k >> 4;
    int mt   = m >> 4;
    int lane = (m & 7) * 4 + ((k & 7) >> 1);
    int j    = (((k & 15) >= 8) ? 2 : 0) + (((m & 15) >= 8) ? 1 : 0);
    unsigned* base = AF + (size_t)(s * 128 + mt * 64) * 4;
    base[lane * 4 + j]        = hi;   // plane 0
    base[(32 + lane) * 4 + j] = lo;   // plane 1
}

// ---------------------------------------------------------------------------
// Kernel 1: segment average   altx[i, c1*32+c2] = mean_t x[c2, c1, i*64+t]
// ---------------------------------------------------------------------------
__global__ void avg_kernel(const float* __restrict__ x, float* __restrict__ altx) {
    int b = blockIdx.x;           // b = c2*64 + c1
    int c2 = b >> 6, c1 = b & 63;
    const float* row = x + (size_t)b * Td;
    __shared__ float ssum[AVGF];
    int tid = threadIdx.x;
    if (tid < AVGF) ssum[tid] = 0.f;
    __syncthreads();
    float local = 0.f;
    int base = tid * 8;
#pragma unroll
    for (int m = 0; m < 8; m++) local += row[base + m];
    atomicAdd(&ssum[tid >> 3], local);
    __syncthreads();
    if (tid < AVGF)
        altx[tid * Md + c1 * 32 + c2] = ssum[tid] * (1.0f / 64.0f);
}

// ---------------------------------------------------------------------------
// A-prep (used once, for altx): A[32,K] fp32 -> fragment layout, 2 planes.
// ---------------------------------------------------------------------------
__global__ void prep_afrag(const float* __restrict__ A, uint4* __restrict__ AF, int K) {
    cudaGridDependencySynchronize();
    int idx = blockIdx.x * blockDim.x + threadIdx.x;
    int total = (K >> 4) << 6;             // (K/16) * 64 threads
    if (idx >= total) return;
    int lane = idx & 31;
    int mt = (idx >> 5) & 1;
    int s = idx >> 6;
    int m = mt * 16 + (lane >> 2);
    int k0 = s * 16 + (lane & 3) * 2;

    float2 a  = *(const float2*)&A[m * K + k0];
    float2 b  = *(const float2*)&A[(m + 8) * K + k0];
    float2 cc = *(const float2*)&A[m * K + k0 + 8];
    float2 d  = *(const float2*)&A[(m + 8) * K + k0 + 8];

    unsigned h0, l0, h1, l1, h2, l2, h3, l3;
    split2(a.x, a.y, h0, l0);
    split2(b.x, b.y, h1, l1);
    split2(cc.x, cc.y, h2, l2);
    split2(d.x, d.y, h3, l3);

    AF[(size_t)s * 128 + (mt * 2 + 0) * 32 + lane] = make_uint4(h0, h1, h2, h3);
    AF[(size_t)s * 128 + (mt * 2 + 1) * 32 + lane] = make_uint4(l0, l1, l2, l3);
}

// ---------------------------------------------------------------------------
// Split-K skinny GEMM — NO shared memory, NO __syncthreads.
//   PART[ky, 32, N] = A[32, kslice] @ W[N, kslice]^T
// PDL: prefetch first weight tiles (pure inputs) BEFORE the grid-dependency
// sync so the prologue overlaps the predecessor's tail; all AF reads and
// PART writes are after the sync.
// ---------------------------------------------------------------------------
template<int SPLITK>
__global__ void __launch_bounds__(128, 5)
gemm_v2(const uint4* __restrict__ AF, const float* __restrict__ W,
        float* __restrict__ PART, int N, int K)
{
    const int tid  = threadIdx.x;
    const int lane = tid & 31;
    const int warp = tid >> 5;
    const int gid  = lane >> 2;   // 0..7
    const int tig  = lane & 3;    // 0..3

    const int n0    = blockIdx.x * 64 + warp * 16;
    const int steps = (K >> 4) / SPLITK;
    const int s0    = blockIdx.y * steps;

    const float* bp0 = W + (size_t)(n0 + gid) * K;       // n8 group 0
    const float* bp1 = W + (size_t)(n0 + 8 + gid) * K;   // n8 group 1
    const int kb = s0 * 16 + tig * 2;

    // prologue weight prefetch (inputs only -> safe pre-sync)
    float2 b0a, b0b, b1a, b1b, x0a, x0b, x1a, x1b;
    b0a = *(const float2*)&bp0[kb];
    b0b = *(const float2*)&bp0[kb + 8];
    b1a = *(const float2*)&bp1[kb];
    b1b = *(const float2*)&bp1[kb + 8];

    cudaGridDependencySynchronize();

    float c[2][2][4] = {};

    for (int s = 0; s < steps; s++) {
        if (s + 1 < steps) {
            int kn = kb + (s + 1) * 16;
            x0a = *(const float2*)&bp0[kn];
            x0b = *(const float2*)&bp0[kn + 8];
            x1a = *(const float2*)&bp1[kn];
            x1b = *(const float2*)&bp1[kn + 8];
        }
        const uint4* af = AF + (size_t)(s0 + s) * 128;
        uint4 ah0 = af[lane];
        uint4 al0 = af[32 + lane];
        uint4 ah1 = af[64 + lane];
        uint4 al1 = af[96 + lane];

        unsigned bh00, bl00, bh01, bl01, bh10, bl10, bh11, bl11;
        split2(b0a.x, b0a.y, bh00, bl00);
        split2(b0b.x, b0b.y, bh01, bl01);
        split2(b1a.x, b1a.y, bh10, bl10);
        split2(b1b.x, b1b.y, bh11, bl11);

        mma_bf16(c[0][0], ah0.x, ah0.y, ah0.z, ah0.w, bh00, bh01);
        mma_bf16(c[0][0], ah0.x, ah0.y, ah0.z, ah0.w, bl00, bl01);
        mma_bf16(c[0][0], al0.x, al0.y, al0.z, al0.w, bh00, bh01);
        mma_bf16(c[1][0], ah1.x, ah1.y, ah1.z, ah1.w, bh00, bh01);
        mma_bf16(c[1][0], ah1.x, ah1.y, ah1.z, ah1.w, bl00, bl01);
        mma_bf16(c[1][0], al1.x, al1.y, al1.z, al1.w, bh00, bh01);
        mma_bf16(c[0][1], ah0.x, ah0.y, ah0.z, ah0.w, bh10, bh11);
        mma_bf16(c[0][1], ah0.x, ah0.y, ah0.z, ah0.w, bl10, bl11);
        mma_bf16(c[0][1], al0.x, al0.y, al0.z, al0.w, bh10, bh11);
        mma_bf16(c[1][1], ah1.x, ah1.y, ah1.z, ah1.w, bh10, bh11);
        mma_bf16(c[1][1], ah1.x, ah1.y, ah1.z, ah1.w, bl10, bl11);
        mma_bf16(c[1][1], al1.x, al1.y, al1.z, al1.w, bh10, bh11);

        b0a = x0a; b0b = x0b; b1a = x1a; b1b = x1b;
    }

    float* base = &PART[(size_t)blockIdx.y * 32 * N];
#pragma unroll
    for (int mt = 0; mt < 2; mt++)
#pragma unroll
        for (int t8 = 0; t8 < 2; t8++) {
            int col = n0 + t8 * 8 + 2 * tig;
            int r0  = mt * 16 + gid;
            *(float2*)&base[r0 * N + col]       = make_float2(c[mt][t8][0], c[mt][t8][1]);
            *(float2*)&base[(r0 + 8) * N + col] = make_float2(c[mt][t8][2], c[mt][t8][3]);
        }
}

// ---------------------------------------------------------------------------
// block-wide sum for 512 threads
// ---------------------------------------------------------------------------
__device__ __forceinline__ float block_sum512(float v, float* sh) {
#pragma unroll
    for (int o = 16; o; o >>= 1) v += __shfl_xor_sync(0xFFFFFFFFu, v, o);
    int w = threadIdx.x >> 5;
    if ((threadIdx.x & 31) == 0) sh[w] = v;
    __syncthreads();
    float r = 0.f;
    if (threadIdx.x < 32) {
        r = (threadIdx.x < 16) ? sh[threadIdx.x] : 0.f;
#pragma unroll
        for (int o = 8; o; o >>= 1) r += __shfl_xor_sync(0xFFFFFFFFu, r, o);
    }
    if (threadIdx.x == 0) sh[0] = r;
    __syncthreads();
    float out = sh[0];
    __syncthreads();
    return out;
}

// ---------------------------------------------------------------------------
// Fused split-K reduce + epilogue + LayerNorm for N=2048. 32 blocks x 512.
// LNMODE: 0 = write OUT_s = v only (final output)
//         1 = write OUT_s = v (raw) and afrag( LN(v)*g+b )          (ln1)
//         2 = write afrag( LN(v)*g+b + v ) only                     (ln2+res)
// ---------------------------------------------------------------------------
template<int SPLITK, int FLAGS, int LNMODE>
__global__ void reduce_ln(const float* __restrict__ PART, const float* __restrict__ bias,
                          const float* __restrict__ resid, float* __restrict__ OUT_s,
                          unsigned* __restrict__ AF, const float* __restrict__ g,
                          const float* __restrict__ bp)
{
    cudaGridDependencySynchronize();
    __shared__ float sh[16];
    const int r = blockIdx.x, tid = threadIdx.x;
    const int c0 = tid * 4;

    float o[4] = {0.f, 0.f, 0.f, 0.f};
#pragma unroll
    for (int p = 0; p < SPLITK; p++) {
        float4 x0 = *(const float4*)&PART[((size_t)p * 32 + r) * Md + c0];
        o[0] += x0.x; o[1] += x0.y; o[2] += x0.z; o[3] += x0.w;
    }
    if (FLAGS & F_BIAS) {
        float4 b0 = *(const float4*)&bias[c0];
        o[0] += b0.x; o[1] += b0.y; o[2] += b0.z; o[3] += b0.w;
    }
    if (FLAGS & F_SIN) {
#pragma unroll
        for (int j = 0; j < 4; j++) {
            int cc = c0 + j;
            int e = cc & ~1;
            float ang = (float)r * powf(10000.0f, -(float)e * (1.0f / 1024.0f));
            o[j] += (cc & 1) ? cosf(ang) : sinf(ang);
        }
    }
    if (FLAGS & F_RES) {
        float4 x0 = *(const float4*)&resid[r * Md + c0];
        o[0] += x0.x; o[1] += x0.y; o[2] += x0.z; o[3] += x0.w;
    }

    if (LNMODE == 0) {
        *(float4*)&OUT_s[r * Md + c0] = make_float4(o[0], o[1], o[2], o[3]);
        return;
    }

    float s = o[0] + o[1] + o[2] + o[3];
    float mean = block_sum512(s, sh) * (1.0f / (float)Md);
    float sq = 0.f;
#pragma unroll
    for (int j = 0; j < 4; j++) { float d = o[j] - mean; sq += d * d; }
    float var = block_sum512(sq, sh) * (1.0f / (float)Md);
    float rstd = rsqrtf(var + 1e-5f);

    float yv[4];
#pragma unroll
    for (int j = 0; j < 4; j++)
        yv[j] = (o[j] - mean) * rstd * g[c0 + j] + bp[c0 + j];

    if (LNMODE == 1) {
        *(float4*)&OUT_s[r * Md + c0] = make_float4(o[0], o[1], o[2], o[3]);
    } else { // LNMODE == 2
#pragma unroll
        for (int j = 0; j < 4; j++) yv[j] += o[j];
    }
    unsigned h0, l0, h1, l1;
    split2(yv[0], yv[1], h0, l0);
    split2(yv[2], yv[3], h1, l1);
    st_afrag(AF, r, c0, h0, l0);
    st_afrag(AF, r, c0 + 2, h1, l1);
}

// ---------------------------------------------------------------------------
// Split-K reduce + bias + GELU -> fragment layout only (FC1 output, N=8192)
// ---------------------------------------------------------------------------
template<int SPLITK>
__global__ void reduce_gelu_frag(const float* __restrict__ PART,
                                 const float* __restrict__ bias,
                                 unsigned* __restrict__ AF, int N)
{
    cudaGridDependencySynchronize();
    int idx = blockIdx.x * blockDim.x + threadIdx.x;
    int n4 = N >> 2;
    if (idx >= 32 * n4) return;
    int r = idx / n4;
    int c = (idx - r * n4) * 4;

    float o[4] = {0.f, 0.f, 0.f, 0.f};
#pragma unroll
    for (int p = 0; p < SPLITK; p++) {
        float4 v = *(const float4*)&PART[((size_t)p * 32 + r) * N + c];
        o[0] += v.x; o[1] += v.y; o[2] += v.z; o[3] += v.w;
    }
    float4 b = *(const float4*)&bias[c];
    o[0] += b.x; o[1] += b.y; o[2] += b.z; o[3] += b.w;
#pragma unroll
    for (int j = 0; j < 4; j++)
        o[j] = 0.5f * o[j] * (1.0f + erff(o[j] * 0.70710678118654752f));

    unsigned h0, l0, h1, l1;
    split2(o[0], o[1], h0, l0);
    split2(o[2], o[3], h1, l1);
    st_afrag(AF, r, c, h0, l0);
    st_afrag(AF, r, c + 2, h1, l1);
}

// ---------------------------------------------------------------------------
// Fused: QKV split-K reduction + scalar attention + serial cumsum.
// grid = 16 heads, 128 threads. Writes imv straight into fragment layout.
// ---------------------------------------------------------------------------
template<int SPLITK>
__global__ void attn_fused(const float* __restrict__ PART, unsigned* __restrict__ AF) {
    cudaGridDependencySynchronize();
    __shared__ float srsa[AVGF];
    int h = blockIdx.x, tid = threadIdx.x;
    int lane = tid & 31, warp = tid >> 5;
    const float inv = 0.088388347648318447f; // 1/sqrt(128)

#pragma unroll
    for (int ii = 0; ii < 8; ii++) {
        int i = ii * 4 + warp;
        float p = 0.f;
#pragma unroll
        for (int j = 0; j < 4; j++) {
            int colq = h * DHd + lane + 32 * j;
            float qv = 0.f, kv = 0.f;
#pragma unroll
            for (int pp = 0; pp < SPLITK; pp++) {
                const float* row = &PART[((size_t)pp * 32 + i) * (3 * Md)];
                qv += row[colq];
                kv += row[Md + colq];
            }
            p = fmaf(qv, kv, p);
        }
#pragma unroll
        for (int o = 16; o; o >>= 1) p += __shfl_xor_sync(0xFFFFFFFFu, p, o);
        if (lane == 0) srsa[i] = p * inv;
    }
    __syncthreads();

    if (tid < 64) {
        int colv = 2 * Md + h * DHd + tid * 2;
        float run0 = 0.f, run1 = 0.f;
#pragma unroll
        for (int i = 0; i < AVGF; i++) {
            float v0 = 0.f, v1 = 0.f;
#pragma unroll
            for (int pp = 0; pp < SPLITK; pp++) {
                float2 vv = *(const float2*)&PART[((size_t)pp * 32 + i) * (3 * Md) + colv];
                v0 += vv.x; v1 += vv.y;
            }
            run0 = fmaf(srsa[i], v0, run0);
            run1 = fmaf(srsa[i], v1, run1);
            unsigned hi, lo;
            split2(run0, run1, hi, lo);
            st_afrag(AF, i, h * DHd + tid * 2, hi, lo);
        }
    }
}

// ---------------------------------------------------------------------------
// host: PDL launch helper
// ---------------------------------------------------------------------------
static inline cudaLaunchConfig_t pdl_cfg(dim3 grid, dim3 block,
                                         cudaLaunchAttribute* at) {
    cudaLaunchConfig_t cfg = {};
    cfg.gridDim = grid;
    cfg.blockDim = block;
    cfg.stream = 0;
    at[0].id = cudaLaunchAttributeProgrammaticStreamSerialization;
    at[0].val.programmaticStreamSerializationAllowed = 1;
    cfg.attrs = at;
    cfg.numAttrs = 1;
    return cfg;
}

// ---------------------------------------------------------------------------
// launch
// ---------------------------------------------------------------------------
extern "C" void kernel_launch(void* const* d_in, const int* in_sizes, int n_in,
                              void* d_out, int out_size) {
    const float* x      = (const float*)d_in[0];
    const float* weight = (const float*)d_in[1];
    const float* Wqkv   = (const float*)d_in[2];
    const float* Wo     = (const float*)d_in[3];
    const float* ln1_g  = (const float*)d_in[4];
    const float* ln1_b  = (const float*)d_in[5];
    const float* ln2_g  = (const float*)d_in[6];
    const float* ln2_b  = (const float*)d_in[7];
    const float* fc1_w  = (const float*)d_in[8];
    const float* fc1_b  = (const float*)d_in[9];
    const float* fc2_w  = (const float*)d_in[10];
    const float* fc2_b  = (const float*)d_in[11];
    float* out = (float*)d_out;

    float *altx, *s, *part;
    uint4* afrag;
    cudaGetSymbolAddress((void**)&altx,  g_altx);
    cudaGetSymbolAddress((void**)&s,     g_s);
    cudaGetSymbolAddress((void**)&part,  g_part);
    cudaGetSymbolAddress((void**)&afrag, g_afrag);
    unsigned* afw = (unsigned*)afrag;

    cudaLaunchAttribute at[1];

    // 1) segment average (plain launch) + one-time A prep (PDL)
    avg_kernel<<<C2d * C1d, 256>>>(x, altx);
    {
        cudaLaunchConfig_t c = pdl_cfg(dim3((Md / 16 * 64 + 255) / 256), dim3(256), at);
        cudaLaunchKernelEx(&c, prep_afrag, (const float*)altx, afrag, (int)Md);
    }

    // 2) s = altx @ weight^T + sin; afrag <- LN1(s)   (splitK=8)
    {
        cudaLaunchConfig_t c = pdl_cfg(dim3(Md / 64, 8), dim3(128), at);
        cudaLaunchKernelEx(&c, gemm_v2<8>, (const uint4*)afrag,
                           (const float*)weight, part, (int)Md, (int)Md);
    }
    {
        cudaLaunchConfig_t c = pdl_cfg(dim3(AVGF), dim3(512), at);
        cudaLaunchKernelEx(&c, reduce_ln<8, F_SIN, 1>, (const float*)part,
                           (const float*)nullptr, (const float*)nullptr, s, afw,
                           ln1_g, ln1_b);
    }

    for (int a = 0; a < TKd; a++) {
        // qkv partials = y @ Wqkv[a]^T   (N=6144, K=2048, splitK=4)
        {
            cudaLaunchConfig_t c = pdl_cfg(dim3((3 * Md) / 64, 4), dim3(128), at);
            cudaLaunchKernelEx(&c, gemm_v2<4>, (const uint4*)afrag,
                               (const float*)(Wqkv + (size_t)a * 3 * Md * Md),
                               part, (int)(3 * Md), (int)Md);
        }
        // fused split-K reduce + attention + cumsum -> afrag(imv)
        {
            cudaLaunchConfig_t c = pdl_cfg(dim3(HAd), dim3(128), at);
            cudaLaunchKernelEx(&c, attn_fused<4>, (const float*)part, afw);
        }

        // s' = imv @ Wo[a]^T + s;  afrag <- LN2(s') + s'   (splitK=8)
        {
            cudaLaunchConfig_t c = pdl_cfg(dim3(Md / 64, 8), dim3(128), at);
            cudaLaunchKernelEx(&c, gemm_v2<8>, (const uint4*)afrag,
                               (const float*)(Wo + (size_t)a * Md * Md),
                               part, (int)Md, (int)Md);
        }
        {
            cudaLaunchConfig_t c = pdl_cfg(dim3(AVGF), dim3(512), at);
            cudaLaunchKernelEx(&c, reduce_ln<8, F_RES, 2>, (const float*)part,
                               (const float*)nullptr, (const float*)s,
                               (float*)nullptr, afw, ln2_g, ln2_b);
        }

        // h partials = s'' @ fc1^T  (N=8192, K=2048, splitK=4)
        {
            cudaLaunchConfig_t c = pdl_cfg(dim3((4 * Md) / 64, 4), dim3(128), at);
            cudaLaunchKernelEx(&c, gemm_v2<4>, (const uint4*)afrag,
                               (const float*)fc1_w, part, (int)(4 * Md), (int)Md);
        }
        {
            cudaLaunchConfig_t c = pdl_cfg(dim3((32 * (4 * Md) / 4 + 127) / 128),
                                           dim3(128), at);
            cudaLaunchKernelEx(&c, reduce_gelu_frag<4>, (const float*)part,
                               (const float*)fc1_b, afw, (int)(4 * Md));
        }

        // s = h @ fc2^T + b        (N=2048, K=8192, splitK=8)
        {
            cudaLaunchConfig_t c = pdl_cfg(dim3(Md / 64, 8), dim3(128), at);
            cudaLaunchKernelEx(&c, gemm_v2<8>, (const uint4*)afrag,
                               (const float*)fc2_w, part, (int)Md, (int)(4 * Md));
        }
        if (a < TKd - 1) {
            cudaLaunchConfig_t c = pdl_cfg(dim3(AVGF), dim3(512), at);
            cudaLaunchKernelEx(&c, reduce_ln<8, F_BIAS, 1>, (const float*)part,
                               fc2_b, (const float*)nullptr, s, afw, ln1_g, ln1_b);
        } else {
            cudaLaunchConfig_t c = pdl_cfg(dim3(AVGF), dim3(512), at);
            cudaLaunchKernelEx(&c, reduce_ln<8, F_BIAS, 0>, (const float*)part,
                               fc2_b, (const float*)nullptr, out,
                               (unsigned*)nullptr, (const float*)nullptr,
                               (const float*)nullptr);
        }
    }
}

// round 16
// speedup vs baseline: 1.1715x; 1.0715x over previous
#include <cuda_runtime.h>
#include <cuda_bf16.h>
#include <math.h>

// ---------------------------------------------------------------------------
// Problem dims
// ---------------------------------------------------------------------------
#define C2d 32
#define C1d 64
#define Td 2048
#define AVGF 32
#define SEG 64
#define Md 2048
#define TKd 3
#define HAd 16
#define DHd 128

// scratch (no allocations allowed -> __device__ globals)
__device__ float g_altx[AVGF * Md];
__device__ float g_s[AVGF * Md];
// split-K partial buffer: max = 8 * 32 * 8192 = 2,097,152 floats (8.4 MB)
__device__ float g_part[2100000];
// A in MMA-fragment layout, 2 bf16 planes: (K/16) * 128 uint4; K<=8192 -> 1MB
__device__ uint4 g_afrag[65536];

#define F_BIAS 1
#define F_RES  2
#define F_GELU 4
#define F_SIN  8

// ---------------------------------------------------------------------------
// helpers: bf16 2-plane split (hi = rn(v), lo = rn(v - hi)); k-pairs packed
// into one 32-bit word (lo half = even k, hi half = odd k).
// ---------------------------------------------------------------------------
__device__ __forceinline__ void split2(float x0, float x1, unsigned& hi, unsigned& lo) {
    asm("cvt.rn.bf16x2.f32 %0, %1, %2;" : "=r"(hi) : "f"(x1), "f"(x0));
    float h0 = __uint_as_float(hi << 16);
    float h1 = __uint_as_float(hi & 0xFFFF0000u);
    float l0 = x0 - h0;
    float l1 = x1 - h1;
    asm("cvt.rn.bf16x2.f32 %0, %1, %2;" : "=r"(lo) : "f"(l1), "f"(l0));
}

__device__ __forceinline__ void mma_bf16(float c[4], unsigned a0, unsigned a1,
                                         unsigned a2, unsigned a3,
                                         unsigned b0, unsigned b1) {
    asm volatile(
        "mma.sync.aligned.m16n8k16.row.col.f32.bf16.bf16.f32 "
        "{%0,%1,%2,%3}, {%4,%5,%6,%7}, {%8,%9}, {%0,%1,%2,%3};"
        : "+f"(c[0]), "+f"(c[1]), "+f"(c[2]), "+f"(c[3])
        : "r"(a0), "r"(a1), "r"(a2), "r"(a3), "r"(b0), "r"(b1));
}

// Store one (m, even-k pair) of a [32,K] activation into the fragment layout
// read by gemm_v2 (inverse of prep_afrag's map; verified in earlier rounds).
__device__ __forceinline__ void st_afrag(unsigned* AF, int m, int k,
                                         unsigned hi, unsigned lo) {
    int s    = k >> 4;
    int mt   = m >> 4;
    int lane = (m & 7) * 4 + ((k & 7) >> 1);
    int j    = (((k & 15) >= 8) ? 2 : 0) + (((m & 15) >= 8) ? 1 : 0);
    unsigned* base = AF + (size_t)(s * 128 + mt * 64) * 4;
    base[lane * 4 + j]        = hi;   // plane 0
    base[(32 + lane) * 4 + j] = lo;   // plane 1
}

// ---------------------------------------------------------------------------
// Kernel 1: segment average   altx[i, c1*32+c2] = mean_t x[c2, c1, i*64+t]
// ---------------------------------------------------------------------------
__global__ void avg_kernel(const float* __restrict__ x, float* __restrict__ altx) {
    int b = blockIdx.x;           // b = c2*64 + c1
    int c2 = b >> 6, c1 = b & 63;
    const float* row = x + (size_t)b * Td;
    __shared__ float ssum[AVGF];
    int tid = threadIdx.x;
    if (tid < AVGF) ssum[tid] = 0.f;
    __syncthreads();
    float local = 0.f;
    int base = tid * 8;
#pragma unroll
    for (int m = 0; m < 8; m++) local += row[base + m];
    atomicAdd(&ssum[tid >> 3], local);
    __syncthreads();
    if (tid < AVGF)
        altx[tid * Md + c1 * 32 + c2] = ssum[tid] * (1.0f / 64.0f);
}

// ---------------------------------------------------------------------------
// A-prep (used once, for altx): A[32,K] fp32 -> fragment layout, 2 planes.
// ---------------------------------------------------------------------------
__global__ void prep_afrag(const float* __restrict__ A, uint4* __restrict__ AF, int K) {
    int idx = blockIdx.x * blockDim.x + threadIdx.x;
    int total = (K >> 4) << 6;             // (K/16) * 64 threads
    if (idx >= total) return;
    int lane = idx & 31;
    int mt = (idx >> 5) & 1;
    int s = idx >> 6;
    int m = mt * 16 + (lane >> 2);
    int k0 = s * 16 + (lane & 3) * 2;

    float2 a  = *(const float2*)&A[m * K + k0];
    float2 b  = *(const float2*)&A[(m + 8) * K + k0];
    float2 cc = *(const float2*)&A[m * K + k0 + 8];
    float2 d  = *(const float2*)&A[(m + 8) * K + k0 + 8];

    unsigned h0, l0, h1, l1, h2, l2, h3, l3;
    split2(a.x, a.y, h0, l0);
    split2(b.x, b.y, h1, l1);
    split2(cc.x, cc.y, h2, l2);
    split2(d.x, d.y, h3, l3);

    AF[(size_t)s * 128 + (mt * 2 + 0) * 32 + lane] = make_uint4(h0, h1, h2, h3);
    AF[(size_t)s * 128 + (mt * 2 + 1) * 32 + lane] = make_uint4(l0, l1, l2, l3);
}

// ---------------------------------------------------------------------------
// Split-K skinny GEMM — NO shared memory, NO __syncthreads.
//   PART[ky, 32, N] = A[32, kslice] @ W[N, kslice]^T
// Both A-fragment loads (L1-broadcast) and B weight loads (DRAM, LDG.128)
// are software-pipelined one k16-step ahead: no serial load->MMA exposure.
// ---------------------------------------------------------------------------
template<int SPLITK>
__global__ void __launch_bounds__(128, 5)
gemm_v2(const uint4* __restrict__ AF, const float* __restrict__ W,
        float* __restrict__ PART, int N, int K)
{
    const int tid  = threadIdx.x;
    const int lane = tid & 31;
    const int warp = tid >> 5;
    const int gid  = lane >> 2;   // 0..7
    const int tig  = lane & 3;    // 0..3

    const int n0    = blockIdx.x * 64 + warp * 16;
    const int steps = (K >> 4) / SPLITK;
    const int s0    = blockIdx.y * steps;

    const float* bp0 = W + (size_t)(n0 + gid) * K;       // n8 group 0
    const float* bp1 = W + (size_t)(n0 + 8 + gid) * K;   // n8 group 1
    const int kb = s0 * 16 + tig * 4;   // each thread covers 4 consecutive k
    // NOTE: lane tig covers k-pairs (2tig, 2tig+1) via float4 at kb = 16s+4*tig?
    // Careful: fragment wants pairs (2t,2t+1) and (2t+8,2t+9) for t=tig.
    // float4 at offset tig*4 gives k = 4tig..4tig+3 -> wrong pairs.
    // Keep the proven float2 pair loads instead (correctness first).

    const int kbp = s0 * 16 + tig * 2;

    // B pipeline registers (one step ahead)
    float2 b0a, b0b, b1a, b1b, x0a, x0b, x1a, x1b;
    b0a = *(const float2*)&bp0[kbp];
    b0b = *(const float2*)&bp0[kbp + 8];
    b1a = *(const float2*)&bp1[kbp];
    b1b = *(const float2*)&bp1[kbp + 8];

    // A pipeline registers (one step ahead)
    const uint4* af0 = AF + (size_t)s0 * 128;
    uint4 ah0 = af0[lane];
    uint4 al0 = af0[32 + lane];
    uint4 ah1 = af0[64 + lane];
    uint4 al1 = af0[96 + lane];

    float c[2][2][4] = {};

    for (int s = 0; s < steps; s++) {
        uint4 nh0, nl0, nh1, nl1;
        if (s + 1 < steps) {
            int kn = kbp + (s + 1) * 16;
            x0a = *(const float2*)&bp0[kn];
            x0b = *(const float2*)&bp0[kn + 8];
            x1a = *(const float2*)&bp1[kn];
            x1b = *(const float2*)&bp1[kn + 8];
            const uint4* af = AF + (size_t)(s0 + s + 1) * 128;
            nh0 = af[lane];
            nl0 = af[32 + lane];
            nh1 = af[64 + lane];
            nl1 = af[96 + lane];
        }

        unsigned bh00, bl00, bh01, bl01, bh10, bl10, bh11, bl11;
        split2(b0a.x, b0a.y, bh00, bl00);
        split2(b0b.x, b0b.y, bh01, bl01);
        split2(b1a.x, b1a.y, bh10, bl10);
        split2(b1b.x, b1b.y, bh11, bl11);

        mma_bf16(c[0][0], ah0.x, ah0.y, ah0.z, ah0.w, bh00, bh01);
        mma_bf16(c[0][0], ah0.x, ah0.y, ah0.z, ah0.w, bl00, bl01);
        mma_bf16(c[0][0], al0.x, al0.y, al0.z, al0.w, bh00, bh01);
        mma_bf16(c[1][0], ah1.x, ah1.y, ah1.z, ah1.w, bh00, bh01);
        mma_bf16(c[1][0], ah1.x, ah1.y, ah1.z, ah1.w, bl00, bl01);
        mma_bf16(c[1][0], al1.x, al1.y, al1.z, al1.w, bh00, bh01);
        mma_bf16(c[0][1], ah0.x, ah0.y, ah0.z, ah0.w, bh10, bh11);
        mma_bf16(c[0][1], ah0.x, ah0.y, ah0.z, ah0.w, bl10, bl11);
        mma_bf16(c[0][1], al0.x, al0.y, al0.z, al0.w, bh10, bh11);
        mma_bf16(c[1][1], ah1.x, ah1.y, ah1.z, ah1.w, bh10, bh11);
        mma_bf16(c[1][1], ah1.x, ah1.y, ah1.z, ah1.w, bl10, bl11);
        mma_bf16(c[1][1], al1.x, al1.y, al1.z, al1.w, bh10, bh11);

        b0a = x0a; b0b = x0b; b1a = x1a; b1b = x1b;
        ah0 = nh0; al0 = nl0; ah1 = nh1; al1 = nl1;
    }

    float* base = &PART[(size_t)blockIdx.y * 32 * N];
#pragma unroll
    for (int mt = 0; mt < 2; mt++)
#pragma unroll
        for (int t8 = 0; t8 < 2; t8++) {
            int col = n0 + t8 * 8 + 2 * tig;
            int r0  = mt * 16 + gid;
            *(float2*)&base[r0 * N + col]       = make_float2(c[mt][t8][0], c[mt][t8][1]);
            *(float2*)&base[(r0 + 8) * N + col] = make_float2(c[mt][t8][2], c[mt][t8][3]);
        }
}

// ---------------------------------------------------------------------------
// block-wide sum for 512 threads
// ---------------------------------------------------------------------------
__device__ __forceinline__ float block_sum512(float v, float* sh) {
#pragma unroll
    for (int o = 16; o; o >>= 1) v += __shfl_xor_sync(0xFFFFFFFFu, v, o);
    int w = threadIdx.x >> 5;
    if ((threadIdx.x & 31) == 0) sh[w] = v;
    __syncthreads();
    float r = 0.f;
    if (threadIdx.x < 32) {
        r = (threadIdx.x < 16) ? sh[threadIdx.x] : 0.f;
#pragma unroll
        for (int o = 8; o; o >>= 1) r += __shfl_xor_sync(0xFFFFFFFFu, r, o);
    }
    if (threadIdx.x == 0) sh[0] = r;
    __syncthreads();
    float out = sh[0];
    __syncthreads();
    return out;
}

// ---------------------------------------------------------------------------
// Fused split-K reduce + epilogue + LayerNorm for N=2048. 32 blocks x 512.
// LNMODE: 0 = write OUT_s = v only (final output)
//         1 = write OUT_s = v (raw) and afrag( LN(v)*g+b )          (ln1)
//         2 = write afrag( LN(v)*g+b + v ) only                     (ln2+res)
// ---------------------------------------------------------------------------
template<int SPLITK, int FLAGS, int LNMODE>
__global__ void reduce_ln(const float* __restrict__ PART, const float* __restrict__ bias,
                          const float* __restrict__ resid, float* __restrict__ OUT_s,
                          unsigned* __restrict__ AF, const float* __restrict__ g,
                          const float* __restrict__ bp)
{
    __shared__ float sh[16];
    const int r = blockIdx.x, tid = threadIdx.x;
    const int c0 = tid * 4;

    float o[4] = {0.f, 0.f, 0.f, 0.f};
#pragma unroll
    for (int p = 0; p < SPLITK; p++) {
        float4 x0 = *(const float4*)&PART[((size_t)p * 32 + r) * Md + c0];
        o[0] += x0.x; o[1] += x0.y; o[2] += x0.z; o[3] += x0.w;
    }
    if (FLAGS & F_BIAS) {
        float4 b0 = *(const float4*)&bias[c0];
        o[0] += b0.x; o[1] += b0.y; o[2] += b0.z; o[3] += b0.w;
    }
    if (FLAGS & F_SIN) {
#pragma unroll
        for (int j = 0; j < 4; j++) {
            int cc = c0 + j;
            int e = cc & ~1;
            float ang = (float)r * powf(10000.0f, -(float)e * (1.0f / 1024.0f));
            o[j] += (cc & 1) ? cosf(ang) : sinf(ang);
        }
    }
    if (FLAGS & F_RES) {
        float4 x0 = *(const float4*)&resid[r * Md + c0];
        o[0] += x0.x; o[1] += x0.y; o[2] += x0.z; o[3] += x0.w;
    }

    if (LNMODE == 0) {
        *(float4*)&OUT_s[r * Md + c0] = make_float4(o[0], o[1], o[2], o[3]);
        return;
    }

    float s = o[0] + o[1] + o[2] + o[3];
    float mean = block_sum512(s, sh) * (1.0f / (float)Md);
    float sq = 0.f;
#pragma unroll
    for (int j = 0; j < 4; j++) { float d = o[j] - mean; sq += d * d; }
    float var = block_sum512(sq, sh) * (1.0f / (float)Md);
    float rstd = rsqrtf(var + 1e-5f);

    float yv[4];
#pragma unroll
    for (int j = 0; j < 4; j++)
        yv[j] = (o[j] - mean) * rstd * g[c0 + j] + bp[c0 + j];

    if (LNMODE == 1) {
        *(float4*)&OUT_s[r * Md + c0] = make_float4(o[0], o[1], o[2], o[3]);
    } else { // LNMODE == 2
#pragma unroll
        for (int j = 0; j < 4; j++) yv[j] += o[j];
    }
    unsigned h0, l0, h1, l1;
    split2(yv[0], yv[1], h0, l0);
    split2(yv[2], yv[3], h1, l1);
    st_afrag(AF, r, c0, h0, l0);
    st_afrag(AF, r, c0 + 2, h1, l1);
}

// ---------------------------------------------------------------------------
// Split-K reduce + bias + GELU -> fragment layout only (FC1 output, N=8192)
// ---------------------------------------------------------------------------
template<int SPLITK>
__global__ void reduce_gelu_frag(const float* __restrict__ PART,
                                 const float* __restrict__ bias,
                                 unsigned* __restrict__ AF, int N)
{
    int idx = blockIdx.x * blockDim.x + threadIdx.x;
    int n4 = N >> 2;
    if (idx >= 32 * n4) return;
    int r = idx / n4;
    int c = (idx - r * n4) * 4;

    float o[4] = {0.f, 0.f, 0.f, 0.f};
#pragma unroll
    for (int p = 0; p < SPLITK; p++) {
        float4 v = *(const float4*)&PART[((size_t)p * 32 + r) * N + c];
        o[0] += v.x; o[1] += v.y; o[2] += v.z; o[3] += v.w;
    }
    float4 b = *(const float4*)&bias[c];
    o[0] += b.x; o[1] += b.y; o[2] += b.z; o[3] += b.w;
#pragma unroll
    for (int j = 0; j < 4; j++)
        o[j] = 0.5f * o[j] * (1.0f + erff(o[j] * 0.70710678118654752f));

    unsigned h0, l0, h1, l1;
    split2(o[0], o[1], h0, l0);
    split2(o[2], o[3], h1, l1);
    st_afrag(AF, r, c, h0, l0);
    st_afrag(AF, r, c + 2, h1, l1);
}

// ---------------------------------------------------------------------------
// Fused: QKV split-K reduction + scalar attention + serial cumsum.
// grid = 16 heads, 128 threads. Writes imv straight into fragment layout.
// ---------------------------------------------------------------------------
template<int SPLITK>
__global__ void attn_fused(const float* __restrict__ PART, unsigned* __restrict__ AF) {
    __shared__ float srsa[AVGF];
    int h = blockIdx.x, tid = threadIdx.x;
    int lane = tid & 31, warp = tid >> 5;
    const float inv = 0.088388347648318447f; // 1/sqrt(128)

#pragma unroll
    for (int ii = 0; ii < 8; ii++) {
        int i = ii * 4 + warp;
        float p = 0.f;
#pragma unroll
        for (int j = 0; j < 4; j++) {
            int colq = h * DHd + lane + 32 * j;
            float qv = 0.f, kv = 0.f;
#pragma unroll
            for (int pp = 0; pp < SPLITK; pp++) {
                const float* row = &PART[((size_t)pp * 32 + i) * (3 * Md)];
                qv += row[colq];
                kv += row[Md + colq];
            }
            p = fmaf(qv, kv, p);
        }
#pragma unroll
        for (int o = 16; o; o >>= 1) p += __shfl_xor_sync(0xFFFFFFFFu, p, o);
        if (lane == 0) srsa[i] = p * inv;
    }
    __syncthreads();

    if (tid < 64) {
        int colv = 2 * Md + h * DHd + tid * 2;
        float run0 = 0.f, run1 = 0.f;
#pragma unroll
        for (int i = 0; i < AVGF; i++) {
            float v0 = 0.f, v1 = 0.f;
#pragma unroll
            for (int pp = 0; pp < SPLITK; pp++) {
                float2 vv = *(const float2*)&PART[((size_t)pp * 32 + i) * (3 * Md) + colv];
                v0 += vv.x; v1 += vv.y;
            }
            run0 = fmaf(srsa[i], v0, run0);
            run1 = fmaf(srsa[i], v1, run1);
            unsigned hi, lo;
            split2(run0, run1, hi, lo);
            st_afrag(AF, i, h * DHd + tid * 2, hi, lo);
        }
    }
}

// ---------------------------------------------------------------------------
// launch  (R13 structure exactly: plain stream-ordered launches, no PDL)
// ---------------------------------------------------------------------------
extern "C" void kernel_launch(void* const* d_in, const int* in_sizes, int n_in,
                              void* d_out, int out_size) {
    const float* x      = (const float*)d_in[0];
    const float* weight = (const float*)d_in[1];
    const float* Wqkv   = (const float*)d_in[2];
    const float* Wo     = (const float*)d_in[3];
    const float* ln1_g  = (const float*)d_in[4];
    const float* ln1_b  = (const float*)d_in[5];
    const float* ln2_g  = (const float*)d_in[6];
    const float* ln2_b  = (const float*)d_in[7];
    const float* fc1_w  = (const float*)d_in[8];
    const float* fc1_b  = (const float*)d_in[9];
    const float* fc2_w  = (const float*)d_in[10];
    const float* fc2_b  = (const float*)d_in[11];
    float* out = (float*)d_out;

    float *altx, *s, *part;
    uint4* afrag;
    cudaGetSymbolAddress((void**)&altx,  g_altx);
    cudaGetSymbolAddress((void**)&s,     g_s);
    cudaGetSymbolAddress((void**)&part,  g_part);
    cudaGetSymbolAddress((void**)&afrag, g_afrag);
    unsigned* afw = (unsigned*)afrag;

    // 1) segment average + one-time A prep
    avg_kernel<<<C2d * C1d, 256>>>(x, altx);
    prep_afrag<<<(Md / 16 * 64 + 255) / 256, 256>>>(altx, afrag, Md);

    // 2) s = altx @ weight^T + sin bias; afrag <- LN1(s)   (splitK=16)
    gemm_v2<16><<<dim3(Md / 64, 16), 128>>>(afrag, weight, part, Md, Md);
    reduce_ln<16, F_SIN, 1><<<AVGF, 512>>>(part, nullptr, nullptr, s, afw,
                                           ln1_g, ln1_b);

    for (int a = 0; a < TKd; a++) {
        // qkv partials = y @ Wqkv[a]^T   (N=6144, K=2048, splitK=4)
        gemm_v2<4><<<dim3((3 * Md) / 64, 4), 128>>>(
            afrag, Wqkv + (size_t)a * 3 * Md * Md, part, 3 * Md, Md);

        // fused split-K reduce + attention + cumsum -> afrag(imv)
        attn_fused<4><<<HAd, 128>>>(part, afw);

        // s' = imv @ Wo[a]^T + s;  afrag <- LN2(s') + s'   (splitK=16)
        gemm_v2<16><<<dim3(Md / 64, 16), 128>>>(
            afrag, Wo + (size_t)a * Md * Md, part, Md, Md);
        reduce_ln<16, F_RES, 2><<<AVGF, 512>>>(part, nullptr, s, nullptr, afw,
                                               ln2_g, ln2_b);

        // h partials = s'' @ fc1^T  (N=8192, K=2048, splitK=8)
        gemm_v2<8><<<dim3((4 * Md) / 64, 8), 128>>>(afrag, fc1_w, part, 4 * Md, Md);
        // afrag <- gelu(h + b)
        reduce_gelu_frag<8><<<(32 * (4 * Md) / 4 + 127) / 128, 128>>>(
            part, fc1_b, afw, 4 * Md);

        // s = h @ fc2^T + b        (N=2048, K=8192, splitK=16)
        gemm_v2<16><<<dim3(Md / 64, 16), 128>>>(afrag, fc2_w, part, Md, 4 * Md);
        if (a < TKd - 1) {
            // write s raw (residual for next Wo stage) + afrag(LN1(s))
            reduce_ln<16, F_BIAS, 1><<<AVGF, 512>>>(part, fc2_b, nullptr, s, afw,
                                                    ln1_g, ln1_b);
        } else {
            reduce_ln<16, F_BIAS, 0><<<AVGF, 512>>>(part, fc2_b, nullptr, out,
                                                    nullptr, nullptr, nullptr);
        }
    }
}